// round 2
// baseline (speedup 1.0000x reference)
#include <cuda_runtime.h>
#include <cuda_bf16.h>
#include <cstdint>

#define M_TOK  8192
#define DIN    4096
#define DOUT   4096
#define RNK    64
#define NEXP   16
#define KG     1024            // NEXP*RNK
#define KTOT   5120            // DIN + KG
#define SCALING 0.5f

// ---------------- scratch (static device globals; no allocations) ----------
__device__ __nv_bfloat16 g_xg_hi[(size_t)M_TOK * KTOT];
__device__ __nv_bfloat16 g_xg_lo[(size_t)M_TOK * KTOT];
__device__ __nv_bfloat16 g_w_hi [(size_t)DOUT * KTOT];
__device__ __nv_bfloat16 g_w_lo [(size_t)DOUT * KTOT];
__device__ __nv_bfloat16 g_w2_hi[128 * DIN];
__device__ __nv_bfloat16 g_w2_lo[128 * DIN];
__device__ float         g_hl   [M_TOK * 128];

// ---------------- helpers ---------------------------------------------------
__device__ __forceinline__ void split_bf(float v, __nv_bfloat16& h, __nv_bfloat16& l) {
    h = __float2bfloat16(v);
    l = __float2bfloat16(v - __bfloat162float(h));
}
__device__ __forceinline__ uint32_t pack2(__nv_bfloat16 a, __nv_bfloat16 b) {
    return (uint32_t)__bfloat16_as_ushort(a) | ((uint32_t)__bfloat16_as_ushort(b) << 16);
}
__device__ __forceinline__ uint32_t smem_u32(const void* p) {
    return (uint32_t)__cvta_generic_to_shared(p);
}

// ---------------- conversion kernels ---------------------------------------
__global__ void convert_x_kernel(const float4* __restrict__ x4) {
    int i = blockIdx.x * blockDim.x + threadIdx.x;      // < M_TOK*DIN/4
    float4 v = x4[i];
    int e = i << 2;
    int row = e >> 12;              // /DIN
    int col = e & (DIN - 1);
    size_t dst = (size_t)row * KTOT + col;
    __nv_bfloat16 h0,h1,h2,h3,l0,l1,l2,l3;
    split_bf(v.x,h0,l0); split_bf(v.y,h1,l1); split_bf(v.z,h2,l2); split_bf(v.w,h3,l3);
    *(uint2*)(g_xg_hi + dst) = make_uint2(pack2(h0,h1), pack2(h2,h3));
    *(uint2*)(g_xg_lo + dst) = make_uint2(pack2(l0,l1), pack2(l2,l3));
}

__global__ void prep_w_kernel(const float* __restrict__ bw, const float* __restrict__ Bm) {
    int i = blockIdx.x * blockDim.x + threadIdx.x;      // < DOUT*KTOT/4
    int e = i << 2;
    int o = e / KTOT;
    int k = e - o * KTOT;
    float4 v;
    if (k < DIN) {
        v = *(const float4*)(bw + (size_t)o * DIN + k);
    } else {
        int kk = k - DIN;
        int ei = kk >> 6, r = kk & 63;
        v = *(const float4*)(Bm + ((size_t)(ei * DOUT + o) * RNK + r));
    }
    size_t dst = (size_t)o * KTOT + k;
    __nv_bfloat16 h0,h1,h2,h3,l0,l1,l2,l3;
    split_bf(v.x,h0,l0); split_bf(v.y,h1,l1); split_bf(v.z,h2,l2); split_bf(v.w,h3,l3);
    *(uint2*)(g_w_hi + dst) = make_uint2(pack2(h0,h1), pack2(h2,h3));
    *(uint2*)(g_w_lo + dst) = make_uint2(pack2(l0,l1), pack2(l2,l3));
}

__global__ void prep_w2_kernel(const float* __restrict__ Am, const float* __restrict__ rw) {
    int i = blockIdx.x * blockDim.x + threadIdx.x;      // < 128*DIN/4
    int e = i << 2;
    int r = e >> 12;
    int k = e & (DIN - 1);
    float4 v = make_float4(0.f, 0.f, 0.f, 0.f);
    if (r < 64)       v = *(const float4*)(Am + (size_t)r * DIN + k);
    else if (r < 80)  v = *(const float4*)(rw + (size_t)(r - 64) * DIN + k);
    size_t dst = (size_t)r * DIN + k;
    __nv_bfloat16 h0,h1,h2,h3,l0,l1,l2,l3;
    split_bf(v.x,h0,l0); split_bf(v.y,h1,l1); split_bf(v.z,h2,l2); split_bf(v.w,h3,l3);
    *(uint2*)(g_w2_hi + dst) = make_uint2(pack2(h0,h1), pack2(h2,h3));
    *(uint2*)(g_w2_lo + dst) = make_uint2(pack2(l0,l1), pack2(l2,l3));
}

// ---------------- router: softmax/top2 + build g rows -----------------------
__global__ void router_kernel() {
    int warp = threadIdx.x >> 5, lane = threadIdx.x & 31;
    int t = blockIdx.x * 8 + warp;                      // 8 warps/block, 1024 blocks
    __shared__ float wsel[8][16];
    if (lane == 0) {
        float lg[16];
        float m = -1e30f;
        #pragma unroll
        for (int e2 = 0; e2 < 16; e2++) { lg[e2] = g_hl[t * 128 + 64 + e2]; m = fmaxf(m, lg[e2]); }
        float p[16]; float Z = 0.f;
        #pragma unroll
        for (int e2 = 0; e2 < 16; e2++) { p[e2] = expf(lg[e2] - m); Z += p[e2]; }
        float inv = 1.f / Z;
        int i1 = 0; float p1 = -1.f;
        #pragma unroll
        for (int e2 = 0; e2 < 16; e2++) if (p[e2] > p1) { p1 = p[e2]; i1 = e2; }
        int i2 = 0; float p2 = -1.f;
        #pragma unroll
        for (int e2 = 0; e2 < 16; e2++) if (e2 != i1 && p[e2] > p2) { p2 = p[e2]; i2 = e2; }
        p1 *= inv; p2 *= inv;
        float denom = p1 + p2 + 1e-6f;
        #pragma unroll
        for (int e2 = 0; e2 < 16; e2++) wsel[warp][e2] = 0.f;
        wsel[warp][i1] = (p1 / denom) * SCALING;
        wsel[warp][i2] = (p2 / denom) * SCALING;
    }
    __syncwarp();
    const float* hrow = g_hl + t * 128;
    size_t base = (size_t)t * KTOT + DIN;
    for (int c = lane; c < KG; c += 32) {
        float v = wsel[warp][c >> 6] * hrow[c & 63];
        __nv_bfloat16 h, l; split_bf(v, h, l);
        g_xg_hi[base + c] = h;
        g_xg_lo[base + c] = l;
    }
}

// ---------------- split-bf16 (3-pass) GEMM: C = A*B^T (+bias) ---------------
// A: [M, Kdim] hi/lo bf16 (row stride lda), B: [N, Kdim] hi/lo (row stride ldb)
// Tiles: 128x128x32, 256 threads (2x4 warps), warp tile 64x32.
#define LDT     40                          // 32 + 8 halves pad (80B rows, 16B aligned)
#define TILEH   (128 * LDT)                 // halves per smem tile
#define STAGEH  (4 * TILEH)                 // Ahi,Alo,Bhi,Blo per stage
#define SMEM_BYTES (2 * STAGEH * 2)         // 81920

#define CPASYNC(dst, src) \
    asm volatile("cp.async.cg.shared.global [%0], [%1], 16;\n" :: "r"(dst), "l"(src))
#define LDSM4(d, addr) \
    asm volatile("ldmatrix.sync.aligned.m8n8.x4.shared.b16 {%0,%1,%2,%3}, [%4];" \
        : "=r"((d)[0]), "=r"((d)[1]), "=r"((d)[2]), "=r"((d)[3]) : "r"(addr))
#define MMA16816(c, a, b) \
    asm volatile("mma.sync.aligned.m16n8k16.row.col.f32.bf16.bf16.f32 " \
        "{%0,%1,%2,%3}, {%4,%5,%6,%7}, {%8,%9}, {%0,%1,%2,%3};" \
        : "+f"((c)[0]), "+f"((c)[1]), "+f"((c)[2]), "+f"((c)[3]) \
        : "r"((a)[0]), "r"((a)[1]), "r"((a)[2]), "r"((a)[3]), "r"((b)[0]), "r"((b)[1]))

__global__ __launch_bounds__(256, 1)
void gemm3_kernel(const __nv_bfloat16* __restrict__ Ahi,
                  const __nv_bfloat16* __restrict__ Alo, int lda,
                  const __nv_bfloat16* __restrict__ Bhi,
                  const __nv_bfloat16* __restrict__ Blo, int ldb,
                  float* __restrict__ C, int ldc,
                  const float* __restrict__ bias, int Kdim)
{
    extern __shared__ __nv_bfloat16 sm[];
    const int tid  = threadIdx.x;
    const int lane = tid & 31, warp = tid >> 5;
    const int wm = warp >> 2, wn = warp & 3;            // 2 x 4 warp grid
    const int bm = blockIdx.y << 7, bn = blockIdx.x << 7;
    const uint32_t smbase = smem_u32(sm);

    // cp.async mapping: chunk c -> row c>>2, col (c&3)*8 halves; 2 chunks/thread/tile
    const int r0 = tid >> 2, q0 = (tid & 3) << 3;
    const int r1 = r0 + 64;
    const uint32_t ob0 = (uint32_t)(r0 * LDT + q0) * 2;
    const uint32_t ob1 = (uint32_t)(r1 * LDT + q0) * 2;

    const __nv_bfloat16* gA0hi = Ahi + (size_t)(bm + r0) * lda + q0;
    const __nv_bfloat16* gA1hi = Ahi + (size_t)(bm + r1) * lda + q0;
    const __nv_bfloat16* gA0lo = Alo + (size_t)(bm + r0) * lda + q0;
    const __nv_bfloat16* gA1lo = Alo + (size_t)(bm + r1) * lda + q0;
    const __nv_bfloat16* gB0hi = Bhi + (size_t)(bn + r0) * ldb + q0;
    const __nv_bfloat16* gB1hi = Bhi + (size_t)(bn + r1) * ldb + q0;
    const __nv_bfloat16* gB0lo = Blo + (size_t)(bn + r0) * ldb + q0;
    const __nv_bfloat16* gB1lo = Blo + (size_t)(bn + r1) * ldb + q0;

    auto issue_stage = [&](int st, int k0) {
        uint32_t sb = smbase + (uint32_t)st * (STAGEH * 2);
        CPASYNC(sb + 0 * (TILEH * 2) + ob0, gA0hi + k0);
        CPASYNC(sb + 0 * (TILEH * 2) + ob1, gA1hi + k0);
        CPASYNC(sb + 1 * (TILEH * 2) + ob0, gA0lo + k0);
        CPASYNC(sb + 1 * (TILEH * 2) + ob1, gA1lo + k0);
        CPASYNC(sb + 2 * (TILEH * 2) + ob0, gB0hi + k0);
        CPASYNC(sb + 2 * (TILEH * 2) + ob1, gB1hi + k0);
        CPASYNC(sb + 3 * (TILEH * 2) + ob0, gB0lo + k0);
        CPASYNC(sb + 3 * (TILEH * 2) + ob1, gB1lo + k0);
        asm volatile("cp.async.commit_group;\n" ::);
    };

    // fragment smem offsets (halves)
    const uint32_t aBase = (uint32_t)((wm * 64 + (lane & 15)) * LDT + ((lane >> 4) << 3));
    const uint32_t bBase = (uint32_t)((wn * 32 + ((lane >> 4) << 3) + (lane & 7)) * LDT
                                      + (((lane >> 3) & 1) << 3));

    float acc[4][4][4] = {};
    const int nk = Kdim >> 5;

    issue_stage(0, 0);
    for (int kt = 0; kt < nk; kt++) {
        if (kt + 1 < nk) {
            issue_stage((kt + 1) & 1, (kt + 1) << 5);
            asm volatile("cp.async.wait_group 1;\n" ::: "memory");
        } else {
            asm volatile("cp.async.wait_group 0;\n" ::: "memory");
        }
        __syncthreads();

        uint32_t sb = smbase + (uint32_t)(kt & 1) * (STAGEH * 2);
        #pragma unroll
        for (int kk = 0; kk < 32; kk += 16) {
            uint32_t ahi[4][4], alo[4][4], bhi[4][2], blo[4][2];
            #pragma unroll
            for (int mi = 0; mi < 4; mi++) {
                uint32_t ad = sb + (aBase + mi * (16 * LDT) + kk) * 2;
                LDSM4(ahi[mi], ad);
                LDSM4(alo[mi], ad + TILEH * 2);
            }
            #pragma unroll
            for (int h = 0; h < 2; h++) {
                uint32_t bd = sb + 2 * (TILEH * 2) + (bBase + h * (16 * LDT) + kk) * 2;
                uint32_t t4[4];
                LDSM4(t4, bd);
                bhi[2*h][0] = t4[0]; bhi[2*h][1] = t4[1];
                bhi[2*h+1][0] = t4[2]; bhi[2*h+1][1] = t4[3];
                LDSM4(t4, bd + TILEH * 2);
                blo[2*h][0] = t4[0]; blo[2*h][1] = t4[1];
                blo[2*h+1][0] = t4[2]; blo[2*h+1][1] = t4[3];
            }
            #pragma unroll
            for (int mi = 0; mi < 4; mi++) {
                #pragma unroll
                for (int nj = 0; nj < 4; nj++) {
                    MMA16816(acc[mi][nj], ahi[mi], bhi[nj]);
                    MMA16816(acc[mi][nj], ahi[mi], blo[nj]);
                    MMA16816(acc[mi][nj], alo[mi], bhi[nj]);
                }
            }
        }
        __syncthreads();
    }

    // epilogue
    const int tr = lane >> 2, tc2 = (lane & 3) << 1;
    #pragma unroll
    for (int mi = 0; mi < 4; mi++) {
        int row = bm + wm * 64 + mi * 16 + tr;
        #pragma unroll
        for (int nj = 0; nj < 4; nj++) {
            int col = bn + wn * 32 + nj * 8 + tc2;
            float b0 = 0.f, b1 = 0.f;
            if (bias) { b0 = bias[col]; b1 = bias[col + 1]; }
            *(float2*)(C + (size_t)row * ldc + col) =
                make_float2(acc[mi][nj][0] + b0, acc[mi][nj][1] + b1);
            *(float2*)(C + (size_t)(row + 8) * ldc + col) =
                make_float2(acc[mi][nj][2] + b0, acc[mi][nj][3] + b1);
        }
    }
}

// ---------------- launch -----------------------------------------------------
extern "C" void kernel_launch(void* const* d_in, const int* in_sizes, int n_in,
                              void* d_out, int out_size)
{
    const float* x  = (const float*)d_in[0];
    const float* bw = (const float*)d_in[1];
    const float* bb = (const float*)d_in[2];
    const float* Am = (const float*)d_in[3];
    const float* Bm = (const float*)d_in[4];
    const float* rw = (const float*)d_in[5];
    float* out = (float*)d_out;

    void *pxh, *pxl, *pwh, *pwl, *pw2h, *pw2l, *phl;
    cudaGetSymbolAddress(&pxh,  g_xg_hi);
    cudaGetSymbolAddress(&pxl,  g_xg_lo);
    cudaGetSymbolAddress(&pwh,  g_w_hi);
    cudaGetSymbolAddress(&pwl,  g_w_lo);
    cudaGetSymbolAddress(&pw2h, g_w2_hi);
    cudaGetSymbolAddress(&pw2l, g_w2_lo);
    cudaGetSymbolAddress(&phl,  g_hl);

    cudaFuncSetAttribute(gemm3_kernel,
                         cudaFuncAttributeMaxDynamicSharedMemorySize, SMEM_BYTES);

    convert_x_kernel<<<(M_TOK * DIN / 4) / 256, 256>>>((const float4*)x);
    prep_w_kernel<<<(DOUT * KTOT / 4) / 256, 256>>>(bw, Bm);
    prep_w2_kernel<<<(128 * DIN / 4) / 256, 256>>>(Am, rw);

    // hidden + router logits: [8192,128] = xg[:, :4096] @ w2^T
    gemm3_kernel<<<dim3(1, 64), 256, SMEM_BYTES>>>(
        (const __nv_bfloat16*)pxh, (const __nv_bfloat16*)pxl, KTOT,
        (const __nv_bfloat16*)pw2h, (const __nv_bfloat16*)pw2l, DIN,
        (float*)phl, 128, nullptr, DIN);

    router_kernel<<<M_TOK / 8, 256>>>();

    // fused main GEMM: out = [x|g] @ [base_w|B_flat]^T + bias
    gemm3_kernel<<<dim3(DOUT / 128, M_TOK / 128), 256, SMEM_BYTES>>>(
        (const __nv_bfloat16*)pxh, (const __nv_bfloat16*)pxl, KTOT,
        (const __nv_bfloat16*)pwh, (const __nv_bfloat16*)pwl, KTOT,
        out, DOUT, bb, KTOT);
}

// round 8
// speedup vs baseline: 2.9367x; 2.9367x over previous
#include <cuda_runtime.h>
#include <cuda_fp16.h>
#include <cstdint>

#define M_TOK   8192
#define DIN     4096
#define DOUT    4096
#define RNK     64
#define NEXP    16
#define KG      1024
#define KTOT    5120
#define SCALING 0.5f

// ---------------- scratch (static device globals; no allocations) -----------
__device__ __half g_xg[(size_t)M_TOK * KTOT];   // 80 MB  [x | g] fp16, row-major
__device__ __half g_wt[(size_t)DOUT * KTOT];    // 40 MB  [base_w | B_flat] fp16
__device__ __half g_w2[128 * DIN];              //  1 MB  [A; router_w; 0] fp16
__device__ float  g_hl[2 * M_TOK * 128];        //  8 MB  split-K partials

// ---------------- helpers ----------------------------------------------------
__device__ __forceinline__ uint32_t smem_u32(const void* p) {
    return (uint32_t)__cvta_generic_to_shared(p);
}
__device__ __forceinline__ uint32_t pack2h(__half a, __half b) {
    return (uint32_t)__half_as_ushort(a) | ((uint32_t)__half_as_ushort(b) << 16);
}

// ---------------- conversion kernels -----------------------------------------
__global__ void convert_x_kernel(const float4* __restrict__ x4) {
    int i = blockIdx.x * blockDim.x + threadIdx.x;      // < M_TOK*DIN/4
    float4 v = x4[i];
    int e = i << 2;
    int row = e >> 12, col = e & (DIN - 1);
    uint2 hp = make_uint2(pack2h(__float2half_rn(v.x), __float2half_rn(v.y)),
                          pack2h(__float2half_rn(v.z), __float2half_rn(v.w)));
    *(uint2*)(g_xg + (size_t)row * KTOT + col) = hp;
}

__global__ void prep_w_kernel(const float* __restrict__ bw, const float* __restrict__ Bm) {
    int i = blockIdx.x * blockDim.x + threadIdx.x;      // < DOUT*KTOT/4
    int e = i << 2;
    int o = e / KTOT, k = e - o * KTOT;
    float4 v;
    if (k < DIN) {
        v = *(const float4*)(bw + (size_t)o * DIN + k);
    } else {
        int kk = k - DIN, ei = kk >> 6, r = kk & 63;
        v = *(const float4*)(Bm + ((size_t)(ei * DOUT + o) * RNK + r));
    }
    *(uint2*)(g_wt + (size_t)o * KTOT + k) =
        make_uint2(pack2h(__float2half_rn(v.x), __float2half_rn(v.y)),
                   pack2h(__float2half_rn(v.z), __float2half_rn(v.w)));
}

__global__ void prep_w2_kernel(const float* __restrict__ Am, const float* __restrict__ rw) {
    int i = blockIdx.x * blockDim.x + threadIdx.x;      // < 128*DIN/4
    int e = i << 2;
    int r = e >> 12, k = e & (DIN - 1);
    float4 v = make_float4(0.f, 0.f, 0.f, 0.f);
    if (r < 64)      v = *(const float4*)(Am + (size_t)r * DIN + k);
    else if (r < 80) v = *(const float4*)(rw + (size_t)(r - 64) * DIN + k);
    *(uint2*)(g_w2 + (size_t)r * DIN + k) =
        make_uint2(pack2h(__float2half_rn(v.x), __float2half_rn(v.y)),
                   pack2h(__float2half_rn(v.z), __float2half_rn(v.w)));
}

// ---------------- router: softmax/top2 -> g columns of g_xg -------------------
__global__ void router_kernel() {
    int warp = threadIdx.x >> 5, lane = threadIdx.x & 31;
    int t = blockIdx.x * 8 + warp;
    __shared__ float wsel[8][16];
    const float* p0 = g_hl + (size_t)t * 128;
    const float* p1 = g_hl + (size_t)M_TOK * 128 + (size_t)t * 128;
    if (lane == 0) {
        float lg[16]; float m = -1e30f;
        #pragma unroll
        for (int e = 0; e < 16; e++) { lg[e] = p0[64 + e] + p1[64 + e]; m = fmaxf(m, lg[e]); }
        float p[16], Z = 0.f;
        #pragma unroll
        for (int e = 0; e < 16; e++) { p[e] = expf(lg[e] - m); Z += p[e]; }
        float inv = 1.f / Z;
        int i1 = 0; float b1 = -1.f;
        #pragma unroll
        for (int e = 0; e < 16; e++) if (p[e] > b1) { b1 = p[e]; i1 = e; }
        int i2 = 0; float b2 = -1.f;
        #pragma unroll
        for (int e = 0; e < 16; e++) if (e != i1 && p[e] > b2) { b2 = p[e]; i2 = e; }
        b1 *= inv; b2 *= inv;
        float den = b1 + b2 + 1e-6f;
        #pragma unroll
        for (int e = 0; e < 16; e++) wsel[warp][e] = 0.f;
        wsel[warp][i1] = (b1 / den) * SCALING;
        wsel[warp][i2] = (b2 / den) * SCALING;
    }
    __syncwarp();
    __half* grow = g_xg + (size_t)t * KTOT + DIN;
    for (int c = lane; c < KG; c += 32) {
        float v = wsel[warp][c >> 6] * (p0[c & 63] + p1[c & 63]);
        grow[c] = __float2half_rn(v);
    }
}

// ---------------- fp16 single-pass GEMM: C = A*B^T (+bias) --------------------
// Tiles 128x128x32, 256 threads (2x4 warps, warp tile 64x32), 3-stage cp.async.
#define LDT     40                          // 32 + 8 halves pad
#define TILEH   (128 * LDT)                 // halves per tile
#define STAGEH  (2 * TILEH)                 // A + B per stage
#define NSTAGE  3
#define SMEM_BYTES (NSTAGE * STAGEH * 2)    // 61440

#define CPASYNC(dst, src) \
    asm volatile("cp.async.cg.shared.global [%0], [%1], 16;\n" :: "r"(dst), "l"(src))
#define LDSM4(d, addr) \
    asm volatile("ldmatrix.sync.aligned.m8n8.x4.shared.b16 {%0,%1,%2,%3}, [%4];" \
        : "=r"((d)[0]), "=r"((d)[1]), "=r"((d)[2]), "=r"((d)[3]) : "r"(addr))
#define MMA16816(c, a, b) \
    asm volatile("mma.sync.aligned.m16n8k16.row.col.f32.f16.f16.f32 " \
        "{%0,%1,%2,%3}, {%4,%5,%6,%7}, {%8,%9}, {%0,%1,%2,%3};" \
        : "+f"((c)[0]), "+f"((c)[1]), "+f"((c)[2]), "+f"((c)[3]) \
        : "r"((a)[0]), "r"((a)[1]), "r"((a)[2]), "r"((a)[3]), "r"((b)[0]), "r"((b)[1]))

extern __shared__ __align__(128) unsigned char smem_buf[];

__global__ __launch_bounds__(256, 2)
void gemm_fp16_kernel(const __half* __restrict__ A, int lda,
                      const __half* __restrict__ B, int ldb,
                      float* __restrict__ C, int ldc,
                      const float* __restrict__ bias, int Kdim)
{
    const int tid = threadIdx.x, lane = tid & 31, warp = tid >> 5;
    const int wm = warp >> 2, wn = warp & 3;            // 2 x 4 warps
    const int bm = blockIdx.y << 7, bn = blockIdx.x << 7;
    const uint32_t smbase = smem_u32(smem_buf);

    // split-K via blockIdx.z (main GEMM: gridDim.z == 1)
    const int koff = blockIdx.z * Kdim;
    A += koff; B += koff;
    C += (size_t)blockIdx.z * M_TOK * ldc;

    const int r0 = tid >> 2, q0 = (tid & 3) << 3, r1 = r0 + 64;
    const uint32_t ob0 = (uint32_t)(r0 * LDT + q0) * 2;
    const uint32_t ob1 = (uint32_t)(r1 * LDT + q0) * 2;

    const __half* gA0 = A + (size_t)(bm + r0) * lda + q0;
    const __half* gA1 = A + (size_t)(bm + r1) * lda + q0;
    const __half* gB0 = B + (size_t)(bn + r0) * ldb + q0;
    const __half* gB1 = B + (size_t)(bn + r1) * ldb + q0;

    auto issue_stage = [&](int st, int k0) {
        uint32_t sb = smbase + (uint32_t)st * (STAGEH * 2);
        CPASYNC(sb + ob0, gA0 + k0);
        CPASYNC(sb + ob1, gA1 + k0);
        CPASYNC(sb + TILEH * 2 + ob0, gB0 + k0);
        CPASYNC(sb + TILEH * 2 + ob1, gB1 + k0);
        asm volatile("cp.async.commit_group;\n" ::);
    };

    const uint32_t aBase = (uint32_t)((wm * 64 + (lane & 15)) * LDT + ((lane >> 4) << 3));
    const uint32_t bBase = (uint32_t)((wn * 32 + ((lane >> 4) << 3) + (lane & 7)) * LDT
                                      + (((lane >> 3) & 1) << 3));
    float acc[4][4][4] = {};
    const int nk = Kdim >> 5;

    issue_stage(0, 0);
    if (nk > 1) issue_stage(1, 32);

    for (int kt = 0; kt < nk; kt++) {
        if (kt + 2 < nk) {
            issue_stage((kt + 2) % NSTAGE, (kt + 2) << 5);
            asm volatile("cp.async.wait_group 2;\n" ::: "memory");
        } else if (kt + 1 < nk) {
            asm volatile("cp.async.wait_group 1;\n" ::: "memory");
        } else {
            asm volatile("cp.async.wait_group 0;\n" ::: "memory");
        }
        __syncthreads();

        uint32_t sb = smbase + (uint32_t)(kt % NSTAGE) * (STAGEH * 2);
        #pragma unroll
        for (int kk = 0; kk < 32; kk += 16) {
            uint32_t a[4][4], b[4][2];
            #pragma unroll
            for (int mi = 0; mi < 4; mi++)
                LDSM4(a[mi], sb + (aBase + mi * (16 * LDT) + kk) * 2);
            #pragma unroll
            for (int h = 0; h < 2; h++) {
                uint32_t t4[4];
                LDSM4(t4, sb + TILEH * 2 + (bBase + h * (16 * LDT) + kk) * 2);
                b[2*h][0] = t4[0]; b[2*h][1] = t4[1];
                b[2*h+1][0] = t4[2]; b[2*h+1][1] = t4[3];
            }
            #pragma unroll
            for (int mi = 0; mi < 4; mi++)
                #pragma unroll
                for (int nj = 0; nj < 4; nj++)
                    MMA16816(acc[mi][nj], a[mi], b[nj]);
        }
        __syncthreads();
    }

    // epilogue
    const int tr = lane >> 2, tc2 = (lane & 3) << 1;
    #pragma unroll
    for (int mi = 0; mi < 4; mi++) {
        int row = bm + wm * 64 + mi * 16 + tr;
        #pragma unroll
        for (int nj = 0; nj < 4; nj++) {
            int col = bn + wn * 32 + nj * 8 + tc2;
            float b0 = 0.f, b1 = 0.f;
            if (bias) { b0 = bias[col]; b1 = bias[col + 1]; }
            *(float2*)(C + (size_t)row * ldc + col) =
                make_float2(acc[mi][nj][0] + b0, acc[mi][nj][1] + b1);
            *(float2*)(C + (size_t)(row + 8) * ldc + col) =
                make_float2(acc[mi][nj][2] + b0, acc[mi][nj][3] + b1);
        }
    }
}

// ---------------- launch ------------------------------------------------------
extern "C" void kernel_launch(void* const* d_in, const int* in_sizes, int n_in,
                              void* d_out, int out_size)
{
    const float* x  = (const float*)d_in[0];
    const float* bw = (const float*)d_in[1];
    const float* bb = (const float*)d_in[2];
    const float* Am = (const float*)d_in[3];
    const float* Bm = (const float*)d_in[4];
    const float* rw = (const float*)d_in[5];
    float* out = (float*)d_out;

    void *pxg, *pwt, *pw2, *phl;
    cudaGetSymbolAddress(&pxg, g_xg);
    cudaGetSymbolAddress(&pwt, g_wt);
    cudaGetSymbolAddress(&pw2, g_w2);
    cudaGetSymbolAddress(&phl, g_hl);

    cudaFuncSetAttribute(gemm_fp16_kernel,
                         cudaFuncAttributeMaxDynamicSharedMemorySize, SMEM_BYTES);

    convert_x_kernel<<<(M_TOK * DIN / 4) / 256, 256>>>((const float4*)x);
    prep_w_kernel<<<(DOUT * KTOT / 4) / 256, 256>>>(bw, Bm);
    prep_w2_kernel<<<(128 * DIN / 4) / 256, 256>>>(Am, rw);

    // hidden + router logits: [8192,128] = x @ w2^T, split-K 2
    gemm_fp16_kernel<<<dim3(1, 64, 2), 256, SMEM_BYTES>>>(
        (const __half*)pxg, KTOT,
        (const __half*)pw2, DIN,
        (float*)phl, 128, nullptr, DIN / 2);

    router_kernel<<<M_TOK / 8, 256>>>();

    // main fused GEMM: out = [x|g] @ [base_w|B_flat]^T + bias
    gemm_fp16_kernel<<<dim3(DOUT / 128, M_TOK / 128, 1), 256, SMEM_BYTES>>>(
        (const __half*)pxg, KTOT,
        (const __half*)pwt, KTOT,
        out, DOUT, bb, KTOT);
}